// round 14
// baseline (speedup 1.0000x reference)
#include <cuda_runtime.h>
#include <cuda_bf16.h>
#include <cstdint>

#define BB 16
#define NN 4096
#define NPOINT 1024
#define NSAMPLE 32
#define M_TOT (BB*NPOINT*NSAMPLE)   // 524288
#define MT 128
#define NBLK (M_TOT/MT)             // 4096
#define FEAT_OUT (BB*128*NPOINT)    // 2097152

// ---------------- device scratch (static, allocation-free) ----------------
__device__ float g_new_xyz[BB*NPOINT*3];
__device__ int   g_group_idx[BB*NPOINT*NSAMPLE];
__device__ float g_feat0[(size_t)4*M_TOT];
__device__ float g_feat1[(size_t)64*M_TOT];
__device__ float g_feat2[(size_t)64*M_TOT];
__device__ float g_feat3[(size_t)128*M_TOT];
__device__ float g_psum[(size_t)128*NBLK];
__device__ float g_psq [(size_t)128*NBLK];
__device__ float g_sum[128];
__device__ float g_sq[128];
__device__ float g_scale[128];
__device__ float g_shift[128];

// v7: SLP log-tree horizontal reduce of [dx2, dy2, dz2, 0]:
//   [dx2+dz2, dy2+0] -> (dx2+dz2)+dy2 ; no FMA anywhere (CPU XLA, Standard fusion)
__device__ __forceinline__ float dist3(float ax, float ay, float az,
                                       float bx, float by, float bz) {
    float dx = ax - bx, dy = ay - by, dz = az - bz;
    float m0 = __fmul_rn(dx, dx);
    float m1 = __fmul_rn(dy, dy);
    float m2 = __fmul_rn(dz, dz);
    return __fadd_rn(__fadd_rn(m0, m2), m1);
}

// packed f32x2 helpers (IEEE rn per lane — bitwise identical to scalar ops)
#define ADD_F32X2(out, a, b) asm("add.rn.f32x2 %0, %1, %2;" : "=l"(out) : "l"(a), "l"(b))
#define MUL_F32X2(out, a, b) asm("mul.rn.f32x2 %0, %1, %2;" : "=l"(out) : "l"(a), "l"(b))
#define PACK_F32X2(out, lo, hi) asm("mov.b64 %0, {%1, %2};" : "=l"(out) : "f"(lo), "f"(hi))
#define UNPACK_F32X2(lo, hi, in) asm("mov.b64 {%0, %1}, %2;" : "=f"(lo), "=f"(hi) : "l"(in))

__device__ __forceinline__ unsigned redux_max_u32(unsigned v) {
    unsigned r; asm("redux.sync.max.u32 %0, %1, 0xffffffff;" : "=r"(r) : "r"(v)); return r;
}
__device__ __forceinline__ unsigned redux_min_u32(unsigned v) {
    unsigned r; asm("redux.sync.min.u32 %0, %1, 0xffffffff;" : "=r"(r) : "r"(v)); return r;
}

// ---------------- 1. FPS: packed math, single barrier, fused u64 warp slots ----------
__global__ __launch_bounds__(512) void fps_kernel(const float* __restrict__ xyz) {
    extern __shared__ float s_coord[];           // sx[4096] sy[4096] sz[4096] = 48KB
    float* sx = s_coord;
    float* sy = s_coord + NN;
    float* sz = s_coord + 2*NN;
    __shared__ unsigned long long warr[2][16];   // (val<<32)|idx per warp, parity-buffered

    const int b = blockIdx.x, tid = threadIdx.x;
    const int wid = tid >> 5, lane = tid & 31;
    const float* xb = xyz + (size_t)b*3*NN;

    float px[8], py[8], pz[8], dl[8];
    unsigned long long pxp[4], pyp[4], pzp[4];
#pragma unroll
    for (int t = 0; t < 8; ++t) {
        int n = tid + t*512;
        px[t] = xb[n]; py[t] = xb[NN + n]; pz[t] = xb[2*NN + n];
        sx[n] = px[t]; sy[n] = py[t]; sz[n] = pz[t];
        dl[t] = 1e10f;
    }
#pragma unroll
    for (int j = 0; j < 4; ++j) {
        PACK_F32X2(pxp[j], px[2*j], px[2*j+1]);
        PACK_F32X2(pyp[j], py[2*j], py[2*j+1]);
        PACK_F32X2(pzp[j], pz[2*j], pz[2*j+1]);
    }
    float cx = xb[0], cy = xb[NN], cz = xb[2*NN];
    __syncthreads();

    for (int it = 0; it < NPOINT; ++it) {
        if (tid == 0) {
            float* nz = &g_new_xyz[(b*NPOINT + it)*3];
            nz[0] = cx; nz[1] = cy; nz[2] = cz;
        }
        unsigned long long ncx2, ncy2, ncz2;
        PACK_F32X2(ncx2, -cx, -cx);
        PACK_F32X2(ncy2, -cy, -cy);
        PACK_F32X2(ncz2, -cz, -cz);

        float bmax = -1.f;
#pragma unroll
        for (int j = 0; j < 4; ++j) {
            unsigned long long dx, dy, dz, m0, m1, m2, t02, d2;
            ADD_F32X2(dx, pxp[j], ncx2);
            ADD_F32X2(dy, pyp[j], ncy2);
            ADD_F32X2(dz, pzp[j], ncz2);
            MUL_F32X2(m0, dx, dx);
            MUL_F32X2(m1, dy, dy);
            MUL_F32X2(m2, dz, dz);
            ADD_F32X2(t02, m0, m2);
            ADD_F32X2(d2, t02, m1);            // (dx2+dz2)+dy2 per lane == v7
            float dlo, dhi;
            UNPACK_F32X2(dlo, dhi, d2);
            float a0 = fminf(dl[2*j],   dlo); dl[2*j]   = a0;
            float a1 = fminf(dl[2*j+1], dhi); dl[2*j+1] = a1;
            bmax = fmaxf(bmax, a0);
            bmax = fmaxf(bmax, a1);
        }
        unsigned mb = __float_as_uint(bmax);
        unsigned wm = redux_max_u32(mb);
        unsigned cand = 0xffffffffu;
        if (mb == wm) {                         // only winning warp(s) pay the scan
#pragma unroll
            for (int t = 7; t >= 0; --t)
                if (__float_as_uint(dl[t]) == wm) cand = (unsigned)(tid + t*512);
        }
        unsigned wi = redux_min_u32(cand);
        const int p = it & 1;
        if (lane == 0) warr[p][wid] = ((unsigned long long)wm << 32) | wi;
        __syncthreads();
        // every warp redundantly reduces across the 16 warps — no 2nd barrier
        unsigned long long e = (lane < 16) ? warr[p][lane] : 0ull;
        unsigned v = (unsigned)(e >> 32);
        unsigned i = (unsigned)e;
        unsigned m  = redux_max_u32(v);
        unsigned c2 = (v == m) ? i : 0xffffffffu;
        unsigned far = redux_min_u32(c2);
        cx = sx[far]; cy = sy[far]; cz = sz[far];
    }
}

// ---------------- 2. stable top-1024 per (b, centroid k<32) via bitonic sort ----------------
__global__ __launch_bounds__(1024) void select_kernel(const float* __restrict__ xyz) {
    __shared__ unsigned long long skeys[4096];
    const int bk = blockIdx.x;
    const int b  = bk >> 5;
    const int kc = bk & 31;
    const int tid = threadIdx.x;
    const float* nz = &g_new_xyz[(b*NPOINT + kc)*3];
    const float cx = nz[0], cy = nz[1], cz = nz[2];
    const float* xb = xyz + (size_t)b*3*NN;
    for (int n = tid; n < NN; n += 1024) {
        float d = dist3(xb[n], xb[NN+n], xb[2*NN+n], cx, cy, cz);
        skeys[n] = ((unsigned long long)__float_as_uint(d) << 32) | (unsigned)n;
    }
    __syncthreads();
    for (int kk = 2; kk <= 4096; kk <<= 1) {
        for (int j = kk >> 1; j > 0; j >>= 1) {
            for (int i = tid; i < 4096; i += 1024) {
                int ixj = i ^ j;
                if (ixj > i) {
                    unsigned long long a = skeys[i], c2 = skeys[ixj];
                    bool up = ((i & kk) == 0);
                    if ((a > c2) == up) { skeys[i] = c2; skeys[ixj] = a; }
                }
            }
            __syncthreads();
        }
    }
    for (int s = tid; s < NPOINT; s += 1024)
        g_group_idx[(b*NPOINT + s)*NSAMPLE + kc] = (int)(skeys[s] & 0xffffffffu);
}

// ---------------- 3. gather + recenter into [4][M] (channel 3 = zero pad) ----------------
__global__ __launch_bounds__(256) void gather_kernel(const float* __restrict__ xyz) {
    int m = blockIdx.x*blockDim.x + threadIdx.x;
    if (m >= M_TOT) return;
    int b = m >> 15;
    int s = (m >> 5) & 1023;
    int gi = g_group_idx[m];
    const float* xb = xyz + (size_t)b*3*NN;
    const float* nz = &g_new_xyz[(b*NPOINT + s)*3];
#pragma unroll
    for (int c = 0; c < 3; ++c)
        g_feat0[(size_t)c*M_TOT + m] = xb[c*NN + gi] - nz[c];
    g_feat0[(size_t)3*M_TOT + m] = 0.f;
}

// ---------------- 4. conv (1x1) + input-side BN/ReLU + stat partials ----------------
template<int CIN, int CINR, int COUT, bool BN_IN>
__global__ __launch_bounds__(256) void conv_kernel(
    const float* __restrict__ in, const float* __restrict__ W,
    const float* __restrict__ bias,
    const float* __restrict__ iscale, const float* __restrict__ ishift,
    float* __restrict__ out, float* __restrict__ psum, float* __restrict__ psq)
{
    extern __shared__ float sh[];
    float* Wsh = sh;                 // COUT*CIN
    float* Ish = sh + COUT*CIN;      // CIN*MT
    const int tid = threadIdx.x;
    const int mbase = blockIdx.x * MT;

    for (int idx = tid; idx < COUT*CIN; idx += 256) {
        int o = idx / CIN, c = idx - o*CIN;
        Wsh[idx] = (c < CINR) ? W[o*CINR + c] : 0.f;
    }
    for (int idx = tid; idx < CIN*MT; idx += 256) {
        int c = idx >> 7, mm = idx & (MT-1);
        float v = in[(size_t)c*M_TOT + mbase + mm];
        if (BN_IN) v = fmaxf(v * iscale[c] + ishift[c], 0.f);
        Ish[idx] = v;
    }
    __syncthreads();

    constexpr int RO = COUT/16;
    const int ty = tid >> 4, tx = tid & 15;
    const int mloc = tx * 8;
    float acc[RO][8];
#pragma unroll
    for (int i = 0; i < RO; ++i)
#pragma unroll
        for (int j = 0; j < 8; ++j) acc[i][j] = 0.f;

#pragma unroll 4
    for (int c = 0; c < CIN; ++c) {
        float4 v0 = *(const float4*)&Ish[c*MT + mloc];
        float4 v1 = *(const float4*)&Ish[c*MT + mloc + 4];
#pragma unroll
        for (int i = 0; i < RO; ++i) {
            float w = Wsh[(ty*RO + i)*CIN + c];
            acc[i][0] = fmaf(w, v0.x, acc[i][0]);
            acc[i][1] = fmaf(w, v0.y, acc[i][1]);
            acc[i][2] = fmaf(w, v0.z, acc[i][2]);
            acc[i][3] = fmaf(w, v0.w, acc[i][3]);
            acc[i][4] = fmaf(w, v1.x, acc[i][4]);
            acc[i][5] = fmaf(w, v1.y, acc[i][5]);
            acc[i][6] = fmaf(w, v1.z, acc[i][6]);
            acc[i][7] = fmaf(w, v1.w, acc[i][7]);
        }
    }
#pragma unroll
    for (int i = 0; i < RO; ++i) {
        const int o = ty*RO + i;
        const float bb = bias[o];
#pragma unroll
        for (int j = 0; j < 8; ++j) acc[i][j] += bb;   // GEMM-then-bias association
        float4 o0 = make_float4(acc[i][0], acc[i][1], acc[i][2], acc[i][3]);
        float4 o1 = make_float4(acc[i][4], acc[i][5], acc[i][6], acc[i][7]);
        *(float4*)&out[(size_t)o*M_TOT + mbase + mloc]     = o0;
        *(float4*)&out[(size_t)o*M_TOT + mbase + mloc + 4] = o1;
        float s = 0.f, q = 0.f;
#pragma unroll
        for (int j = 0; j < 8; ++j) { s += acc[i][j]; q += acc[i][j]*acc[i][j]; }
#pragma unroll
        for (int off = 8; off > 0; off >>= 1) {
            s += __shfl_xor_sync(0xffffffffu, s, off);
            q += __shfl_xor_sync(0xffffffffu, q, off);
        }
        if (tx == 0) {
            psum[(size_t)o*NBLK + blockIdx.x] = s;
            psq [(size_t)o*NBLK + blockIdx.x] = q;
        }
    }
}

// ---------------- 5. deterministic stat reduction (sum & sq in one launch) ----------------
__global__ __launch_bounds__(256) void reduce_kernel(const float* __restrict__ psum,
                                                     const float* __restrict__ psq,
                                                     float* __restrict__ osum,
                                                     float* __restrict__ osq) {
    __shared__ float red[256];
    const int o = blockIdx.x, tid = threadIdx.x;
    const float* row = (blockIdx.y ? psq : psum) + (size_t)o*NBLK;
    float* outv = blockIdx.y ? osq : osum;
    float s = 0.f;
    for (int i = tid; i < NBLK; i += 256) s += row[i];
    red[tid] = s; __syncthreads();
    for (int st = 128; st > 0; st >>= 1) {
        if (tid < st) red[tid] += red[tid + st];
        __syncthreads();
    }
    if (tid == 0) outv[o] = red[0];
}

__global__ void bn_kernel(const float* __restrict__ gamma, const float* __restrict__ beta,
                          int cout) {
    int o = threadIdx.x;
    if (o >= cout) return;
    const float inv = 1.0f / (float)M_TOT;
    float mean = g_sum[o] * inv;
    float var  = g_sq[o] * inv - mean*mean;
    if (var < 0.f) var = 0.f;
    float sc = gamma[o] / sqrtf(var + 1e-5f);
    g_scale[o] = sc;
    g_shift[o] = beta[o] - mean * sc;
}

// ---------------- 6. BN3 + ReLU + max over K (coalesced transpose-read) ----------------
__global__ __launch_bounds__(256) void final_kernel(float* __restrict__ outF) {
    const int wu   = blockIdx.x*8 + (threadIdx.x >> 5);   // 0..65535
    const int lane = threadIdx.x & 31;
    const int schunk = wu & 31;
    const int o = (wu >> 5) & 127;
    const int b = wu >> 12;
    const float sc = g_scale[o], sf = g_shift[o];
    const size_t rowbase = (size_t)o*M_TOT + ((size_t)b << 15) + ((size_t)schunk << 10);
    float keep = 0.f;
#pragma unroll
    for (int j = 0; j < 32; ++j) {
        float v = g_feat3[rowbase + j*32 + lane];      // coalesced 128B per iter
        float y = fmaxf(fmaf(v, sc, sf), 0.f);         // relu(bn) >= 0
        unsigned r = redux_max_u32(__float_as_uint(y));
        if (lane == j) keep = __uint_as_float(r);
    }
    outF[((size_t)b << 17) + ((size_t)o << 10) + (schunk*32 + lane)] = keep;
}

__global__ void xyz_out_kernel(float* __restrict__ outX) {
    int idx = blockIdx.x*blockDim.x + threadIdx.x;
    if (idx >= BB*3*NPOINT) return;
    int s = idx & 1023;
    int c = (idx >> 10) % 3;
    int b = idx / (3*NPOINT);
    outX[idx] = g_new_xyz[(b*NPOINT + s)*3 + c];
}

// ---------------- launch ----------------
extern "C" void kernel_launch(void* const* d_in, const int* in_sizes, int n_in,
                              void* d_out, int out_size) {
    (void)in_sizes; (void)n_in; (void)out_size;
    const float* xyz = (const float*)d_in[0];
    const float* W0 = (const float*)d_in[1];
    const float* b0 = (const float*)d_in[2];
    const float* g0 = (const float*)d_in[3];
    const float* be0= (const float*)d_in[4];
    const float* W1 = (const float*)d_in[5];
    const float* b1 = (const float*)d_in[6];
    const float* g1 = (const float*)d_in[7];
    const float* be1= (const float*)d_in[8];
    const float* W2 = (const float*)d_in[9];
    const float* b2 = (const float*)d_in[10];
    const float* g2 = (const float*)d_in[11];
    const float* be2= (const float*)d_in[12];
    float* outp = (float*)d_out;

    void *p_f0, *p_f1, *p_f2, *p_f3, *p_ps, *p_pq, *p_sum, *p_sq;
    cudaGetSymbolAddress(&p_f0, g_feat0);
    cudaGetSymbolAddress(&p_f1, g_feat1);
    cudaGetSymbolAddress(&p_f2, g_feat2);
    cudaGetSymbolAddress(&p_f3, g_feat3);
    cudaGetSymbolAddress(&p_ps, g_psum);
    cudaGetSymbolAddress(&p_pq, g_psq);
    cudaGetSymbolAddress(&p_sum, g_sum);
    cudaGetSymbolAddress(&p_sq, g_sq);

    const int smemF = 3*NN*4;                 // 48KB coords for fps
    cudaFuncSetAttribute((const void*)fps_kernel,
                         cudaFuncAttributeMaxDynamicSharedMemorySize, smemF);
    const int smem1 = (64*4   + 4*MT)  * 4;   //  3 KB
    const int smem2 = (64*64  + 64*MT) * 4;   // 48 KB
    const int smem3 = (128*64 + 64*MT) * 4;   // 64 KB
    cudaFuncSetAttribute((const void*)conv_kernel<64,64,64,true>,
                         cudaFuncAttributeMaxDynamicSharedMemorySize, smem2);
    cudaFuncSetAttribute((const void*)conv_kernel<64,64,128,true>,
                         cudaFuncAttributeMaxDynamicSharedMemorySize, smem3);

    void *p_sc, *p_sh;
    cudaGetSymbolAddress(&p_sc, g_scale);
    cudaGetSymbolAddress(&p_sh, g_shift);

    fps_kernel<<<BB, 512, smemF>>>(xyz);
    select_kernel<<<BB*NSAMPLE, 1024>>>(xyz);
    gather_kernel<<<(M_TOT+255)/256, 256>>>(xyz);

    // layer 1: 3 -> 64 (no input BN)
    conv_kernel<4,3,64,false><<<NBLK, 256, smem1>>>(
        (const float*)p_f0, W0, b0, nullptr, nullptr,
        (float*)p_f1, (float*)p_ps, (float*)p_pq);
    reduce_kernel<<<dim3(64,2), 256>>>((const float*)p_ps, (const float*)p_pq,
                                       (float*)p_sum, (float*)p_sq);
    bn_kernel<<<1, 128>>>(g0, be0, 64);

    // layer 2: 64 -> 64 (BN1+ReLU applied on input)
    conv_kernel<64,64,64,true><<<NBLK, 256, smem2>>>(
        (const float*)p_f1, W1, b1, (const float*)p_sc, (const float*)p_sh,
        (float*)p_f2, (float*)p_ps, (float*)p_pq);
    reduce_kernel<<<dim3(64,2), 256>>>((const float*)p_ps, (const float*)p_pq,
                                       (float*)p_sum, (float*)p_sq);
    bn_kernel<<<1, 128>>>(g1, be1, 64);

    // layer 3: 64 -> 128 (BN2+ReLU applied on input)
    conv_kernel<64,64,128,true><<<NBLK, 256, smem3>>>(
        (const float*)p_f2, W2, b2, (const float*)p_sc, (const float*)p_sh,
        (float*)p_f3, (float*)p_ps, (float*)p_pq);
    reduce_kernel<<<dim3(128,2), 256>>>((const float*)p_ps, (const float*)p_pq,
                                        (float*)p_sum, (float*)p_sq);
    bn_kernel<<<1, 128>>>(g2, be2, 128);

    // BN3 + ReLU + max over K -> features; then new_xyz transpose
    final_kernel<<<8192, 256>>>(outp);
    xyz_out_kernel<<<(BB*3*NPOINT+255)/256, 256>>>(outp + FEAT_OUT);
}

// round 17
// speedup vs baseline: 1.0499x; 1.0499x over previous
#include <cuda_runtime.h>
#include <cuda_bf16.h>
#include <cstdint>

#define BB 16
#define NN 4096
#define NPOINT 1024
#define NSAMPLE 32
#define M_TOT (BB*NPOINT*NSAMPLE)   // 524288
#define MT 128
#define NBLK (M_TOT/MT)             // 4096
#define FEAT_OUT (BB*128*NPOINT)    // 2097152
#define BS_TOT (BB*NPOINT)          // 16384

// ---------------- device scratch (static, allocation-free) ----------------
__device__ float g_new_xyz[BB*NPOINT*3];
__device__ int   g_group_idx[BB*NPOINT*NSAMPLE];
__device__ float g_feat0[(size_t)4*M_TOT];
__device__ float g_feat1[(size_t)64*M_TOT];
__device__ float g_feat2[(size_t)64*M_TOT];
__device__ float g_mx[(size_t)128*BS_TOT];   // per-(o,b,s) max over k of conv3 y
__device__ float g_mn[(size_t)128*BS_TOT];   // per-(o,b,s) min over k of conv3 y
__device__ float g_psum[(size_t)128*NBLK];
__device__ float g_psq [(size_t)128*NBLK];
__device__ float g_sum[128];
__device__ float g_sq[128];
__device__ float g_scale[128];
__device__ float g_shift[128];

// v7: SLP log-tree horizontal reduce of [dx2, dy2, dz2, 0]:
//   [dx2+dz2, dy2+0] -> (dx2+dz2)+dy2 ; no FMA anywhere (CPU XLA, Standard fusion)
__device__ __forceinline__ float dist3(float ax, float ay, float az,
                                       float bx, float by, float bz) {
    float dx = ax - bx, dy = ay - by, dz = az - bz;
    float m0 = __fmul_rn(dx, dx);
    float m1 = __fmul_rn(dy, dy);
    float m2 = __fmul_rn(dz, dz);
    return __fadd_rn(__fadd_rn(m0, m2), m1);
}

// packed f32x2 helpers (IEEE rn per lane — bitwise identical to scalar ops)
#define ADD_F32X2(out, a, b) asm("add.rn.f32x2 %0, %1, %2;" : "=l"(out) : "l"(a), "l"(b))
#define MUL_F32X2(out, a, b) asm("mul.rn.f32x2 %0, %1, %2;" : "=l"(out) : "l"(a), "l"(b))
#define PACK_F32X2(out, lo, hi) asm("mov.b64 %0, {%1, %2};" : "=l"(out) : "f"(lo), "f"(hi))
#define UNPACK_F32X2(lo, hi, in) asm("mov.b64 {%0, %1}, %2;" : "=f"(lo), "=f"(hi) : "l"(in))

__device__ __forceinline__ unsigned redux_max_u32(unsigned v) {
    unsigned r; asm("redux.sync.max.u32 %0, %1, 0xffffffff;" : "=r"(r) : "r"(v)); return r;
}
__device__ __forceinline__ unsigned redux_min_u32(unsigned v) {
    unsigned r; asm("redux.sync.min.u32 %0, %1, 0xffffffff;" : "=r"(r) : "r"(v)); return r;
}

// ---------------- 1. FPS: packed math, single barrier, fused u64 warp slots ----------
__global__ __launch_bounds__(512) void fps_kernel(const float* __restrict__ xyz) {
    extern __shared__ float s_coord[];           // sx[4096] sy[4096] sz[4096] = 48KB
    float* sx = s_coord;
    float* sy = s_coord + NN;
    float* sz = s_coord + 2*NN;
    __shared__ unsigned long long warr[2][16];   // (val<<32)|idx per warp, parity-buffered

    const int b = blockIdx.x, tid = threadIdx.x;
    const int wid = tid >> 5, lane = tid & 31;
    const float* xb = xyz + (size_t)b*3*NN;

    float px[8], py[8], pz[8], dl[8];
    unsigned long long pxp[4], pyp[4], pzp[4];
#pragma unroll
    for (int t = 0; t < 8; ++t) {
        int n = tid + t*512;
        px[t] = xb[n]; py[t] = xb[NN + n]; pz[t] = xb[2*NN + n];
        sx[n] = px[t]; sy[n] = py[t]; sz[n] = pz[t];
        dl[t] = 1e10f;
    }
#pragma unroll
    for (int j = 0; j < 4; ++j) {
        PACK_F32X2(pxp[j], px[2*j], px[2*j+1]);
        PACK_F32X2(pyp[j], py[2*j], py[2*j+1]);
        PACK_F32X2(pzp[j], pz[2*j], pz[2*j+1]);
    }
    float cx = xb[0], cy = xb[NN], cz = xb[2*NN];
    __syncthreads();

    for (int it = 0; it < NPOINT; ++it) {
        if (tid == 0) {
            float* nz = &g_new_xyz[(b*NPOINT + it)*3];
            nz[0] = cx; nz[1] = cy; nz[2] = cz;
        }
        unsigned long long ncx2, ncy2, ncz2;
        PACK_F32X2(ncx2, -cx, -cx);
        PACK_F32X2(ncy2, -cy, -cy);
        PACK_F32X2(ncz2, -cz, -cz);

        float bmax = -1.f;
#pragma unroll
        for (int j = 0; j < 4; ++j) {
            unsigned long long dx, dy, dz, m0, m1, m2, t02, d2;
            ADD_F32X2(dx, pxp[j], ncx2);
            ADD_F32X2(dy, pyp[j], ncy2);
            ADD_F32X2(dz, pzp[j], ncz2);
            MUL_F32X2(m0, dx, dx);
            MUL_F32X2(m1, dy, dy);
            MUL_F32X2(m2, dz, dz);
            ADD_F32X2(t02, m0, m2);
            ADD_F32X2(d2, t02, m1);            // (dx2+dz2)+dy2 per lane == v7
            float dlo, dhi;
            UNPACK_F32X2(dlo, dhi, d2);
            float a0 = fminf(dl[2*j],   dlo); dl[2*j]   = a0;
            float a1 = fminf(dl[2*j+1], dhi); dl[2*j+1] = a1;
            bmax = fmaxf(bmax, a0);
            bmax = fmaxf(bmax, a1);
        }
        unsigned mb = __float_as_uint(bmax);
        unsigned wm = redux_max_u32(mb);
        unsigned cand = 0xffffffffu;
        if (mb == wm) {                         // only winning warp(s) pay the scan
#pragma unroll
            for (int t = 7; t >= 0; --t)
                if (__float_as_uint(dl[t]) == wm) cand = (unsigned)(tid + t*512);
        }
        unsigned wi = redux_min_u32(cand);
        const int p = it & 1;
        if (lane == 0) warr[p][wid] = ((unsigned long long)wm << 32) | wi;
        __syncthreads();
        // every warp redundantly reduces across the 16 warps — no 2nd barrier
        unsigned long long e = (lane < 16) ? warr[p][lane] : 0ull;
        unsigned v = (unsigned)(e >> 32);
        unsigned i = (unsigned)e;
        unsigned m  = redux_max_u32(v);
        unsigned c2 = (v == m) ? i : 0xffffffffu;
        unsigned far = redux_min_u32(c2);
        cx = sx[far]; cy = sy[far]; cz = sz[far];
    }
}

// ---------------- 2. stable top-1024 per (b, centroid k<32) via bitonic sort ----------------
__global__ __launch_bounds__(1024) void select_kernel(const float* __restrict__ xyz) {
    __shared__ unsigned long long skeys[4096];
    const int bk = blockIdx.x;
    const int b  = bk >> 5;
    const int kc = bk & 31;
    const int tid = threadIdx.x;
    const float* nz = &g_new_xyz[(b*NPOINT + kc)*3];
    const float cx = nz[0], cy = nz[1], cz = nz[2];
    const float* xb = xyz + (size_t)b*3*NN;
    for (int n = tid; n < NN; n += 1024) {
        float d = dist3(xb[n], xb[NN+n], xb[2*NN+n], cx, cy, cz);
        skeys[n] = ((unsigned long long)__float_as_uint(d) << 32) | (unsigned)n;
    }
    __syncthreads();
    for (int kk = 2; kk <= 4096; kk <<= 1) {
        for (int j = kk >> 1; j > 0; j >>= 1) {
            for (int i = tid; i < 4096; i += 1024) {
                int ixj = i ^ j;
                if (ixj > i) {
                    unsigned long long a = skeys[i], c2 = skeys[ixj];
                    bool up = ((i & kk) == 0);
                    if ((a > c2) == up) { skeys[i] = c2; skeys[ixj] = a; }
                }
            }
            __syncthreads();
        }
    }
    for (int s = tid; s < NPOINT; s += 1024)
        g_group_idx[(b*NPOINT + s)*NSAMPLE + kc] = (int)(skeys[s] & 0xffffffffu);
}

// ---------------- 3. gather + recenter into [4][M] (channel 3 = zero pad) ----------------
__global__ __launch_bounds__(256) void gather_kernel(const float* __restrict__ xyz) {
    int m = blockIdx.x*blockDim.x + threadIdx.x;
    if (m >= M_TOT) return;
    int b = m >> 15;
    int s = (m >> 5) & 1023;
    int gi = g_group_idx[m];
    const float* xb = xyz + (size_t)b*3*NN;
    const float* nz = &g_new_xyz[(b*NPOINT + s)*3];
#pragma unroll
    for (int c = 0; c < 3; ++c)
        g_feat0[(size_t)c*M_TOT + m] = xb[c*NN + gi] - nz[c];
    g_feat0[(size_t)3*M_TOT + m] = 0.f;
}

// ---------------- 4. conv (1x1) + input-side BN/ReLU + stat partials ----------------
// KRED=false: write full [COUT][M] output. KRED=true: write per-(o,b,s) max/min over k.
template<int CIN, int CINR, int COUT, bool BN_IN, bool KRED>
__global__ __launch_bounds__(256) void conv_kernel(
    const float* __restrict__ in, const float* __restrict__ W,
    const float* __restrict__ bias,
    const float* __restrict__ iscale, const float* __restrict__ ishift,
    float* __restrict__ out, float* __restrict__ outmn,
    float* __restrict__ psum, float* __restrict__ psq)
{
    extern __shared__ float sh[];
    float* Wsh = sh;                 // COUT*CIN
    float* Ish = sh + COUT*CIN;      // CIN*MT
    const int tid = threadIdx.x;
    const int mbase = blockIdx.x * MT;

    for (int idx = tid; idx < COUT*CIN; idx += 256) {
        int o = idx / CIN, c = idx - o*CIN;
        Wsh[idx] = (c < CINR) ? W[o*CINR + c] : 0.f;
    }
    for (int idx = tid; idx < CIN*MT; idx += 256) {
        int c = idx >> 7, mm = idx & (MT-1);
        float v = in[(size_t)c*M_TOT + mbase + mm];
        if (BN_IN) v = fmaxf(v * iscale[c] + ishift[c], 0.f);
        Ish[idx] = v;
    }
    __syncthreads();

    constexpr int RO = COUT/16;
    const int ty = tid >> 4, tx = tid & 15;
    const int mloc = tx * 8;
    float acc[RO][8];
#pragma unroll
    for (int i = 0; i < RO; ++i)
#pragma unroll
        for (int j = 0; j < 8; ++j) acc[i][j] = 0.f;

#pragma unroll 4
    for (int c = 0; c < CIN; ++c) {
        float4 v0 = *(const float4*)&Ish[c*MT + mloc];
        float4 v1 = *(const float4*)&Ish[c*MT + mloc + 4];
#pragma unroll
        for (int i = 0; i < RO; ++i) {
            float w = Wsh[(ty*RO + i)*CIN + c];
            acc[i][0] = fmaf(w, v0.x, acc[i][0]);
            acc[i][1] = fmaf(w, v0.y, acc[i][1]);
            acc[i][2] = fmaf(w, v0.z, acc[i][2]);
            acc[i][3] = fmaf(w, v0.w, acc[i][3]);
            acc[i][4] = fmaf(w, v1.x, acc[i][4]);
            acc[i][5] = fmaf(w, v1.y, acc[i][5]);
            acc[i][6] = fmaf(w, v1.z, acc[i][6]);
            acc[i][7] = fmaf(w, v1.w, acc[i][7]);
        }
    }
#pragma unroll
    for (int i = 0; i < RO; ++i) {
        const int o = ty*RO + i;
        const float bb = bias[o];
#pragma unroll
        for (int j = 0; j < 8; ++j) acc[i][j] += bb;   // GEMM-then-bias association

        if (KRED) {
            // 8 accs are 8 consecutive k within one s; reduce to 32-k max/min
            float mx = acc[i][0], mn = acc[i][0];
#pragma unroll
            for (int j = 1; j < 8; ++j) { mx = fmaxf(mx, acc[i][j]); mn = fminf(mn, acc[i][j]); }
#pragma unroll
            for (int off = 1; off <= 2; off <<= 1) {
                mx = fmaxf(mx, __shfl_xor_sync(0xffffffffu, mx, off));
                mn = fminf(mn, __shfl_xor_sync(0xffffffffu, mn, off));
            }
            if ((tx & 3) == 0) {
                int bs = (mbase >> 5) + (tx >> 2);   // global (b,s) index
                out  [(size_t)o*BS_TOT + bs] = mx;
                outmn[(size_t)o*BS_TOT + bs] = mn;
            }
        } else {
            float4 o0 = make_float4(acc[i][0], acc[i][1], acc[i][2], acc[i][3]);
            float4 o1 = make_float4(acc[i][4], acc[i][5], acc[i][6], acc[i][7]);
            *(float4*)&out[(size_t)o*M_TOT + mbase + mloc]     = o0;
            *(float4*)&out[(size_t)o*M_TOT + mbase + mloc + 4] = o1;
        }

        float s = 0.f, q = 0.f;
#pragma unroll
        for (int j = 0; j < 8; ++j) { s += acc[i][j]; q += acc[i][j]*acc[i][j]; }
#pragma unroll
        for (int off = 8; off > 0; off >>= 1) {
            s += __shfl_xor_sync(0xffffffffu, s, off);
            q += __shfl_xor_sync(0xffffffffu, q, off);
        }
        if (tx == 0) {
            psum[(size_t)o*NBLK + blockIdx.x] = s;
            psq [(size_t)o*NBLK + blockIdx.x] = q;
        }
    }
}

// ---------------- 5. deterministic stat reduction (sum & sq in one launch) ----------------
__global__ __launch_bounds__(256) void reduce_kernel(const float* __restrict__ psum,
                                                     const float* __restrict__ psq,
                                                     float* __restrict__ osum,
                                                     float* __restrict__ osq) {
    __shared__ float red[256];
    const int o = blockIdx.x, tid = threadIdx.x;
    const float* row = (blockIdx.y ? psq : psum) + (size_t)o*NBLK;
    float* outv = blockIdx.y ? osq : osum;
    float s = 0.f;
    for (int i = tid; i < NBLK; i += 256) s += row[i];
    red[tid] = s; __syncthreads();
    for (int st = 128; st > 0; st >>= 1) {
        if (tid < st) red[tid] += red[tid + st];
        __syncthreads();
    }
    if (tid == 0) outv[o] = red[0];
}

__global__ void bn_kernel(const float* __restrict__ gamma, const float* __restrict__ beta,
                          int cout) {
    int o = threadIdx.x;
    if (o >= cout) return;
    const float inv = 1.0f / (float)M_TOT;
    float mean = g_sum[o] * inv;
    float var  = g_sq[o] * inv - mean*mean;
    if (var < 0.f) var = 0.f;
    float sc = gamma[o] / sqrtf(var + 1e-5f);
    g_scale[o] = sc;
    g_shift[o] = beta[o] - mean * sc;
}

// ---------------- 6. BN3 + ReLU on the k-reduced extremes ----------------
// max_k relu(fmaf(y_k,sc,sf)) == relu(fmaf(sc>=0 ? max_k y : min_k y, sc, sf))
// (fp rounding is monotone; relu monotone) — bitwise identical to the full scan.
__global__ __launch_bounds__(256) void final_kernel(float* __restrict__ outF) {
    int idx = blockIdx.x*blockDim.x + threadIdx.x;
    if (idx >= FEAT_OUT) return;
    int s = idx & 1023;
    int o = (idx >> 10) & 127;
    int b = idx >> 17;
    float sc = g_scale[o], sf = g_shift[o];
    size_t p = (size_t)o*BS_TOT + ((size_t)b << 10) + s;
    float v = (sc >= 0.f) ? g_mx[p] : g_mn[p];
    outF[idx] = fmaxf(fmaf(v, sc, sf), 0.f);
}

__global__ void xyz_out_kernel(float* __restrict__ outX) {
    int idx = blockIdx.x*blockDim.x + threadIdx.x;
    if (idx >= BB*3*NPOINT) return;
    int s = idx & 1023;
    int c = (idx >> 10) % 3;
    int b = idx / (3*NPOINT);
    outX[idx] = g_new_xyz[(b*NPOINT + s)*3 + c];
}

// ---------------- launch ----------------
extern "C" void kernel_launch(void* const* d_in, const int* in_sizes, int n_in,
                              void* d_out, int out_size) {
    (void)in_sizes; (void)n_in; (void)out_size;
    const float* xyz = (const float*)d_in[0];
    const float* W0 = (const float*)d_in[1];
    const float* b0 = (const float*)d_in[2];
    const float* g0 = (const float*)d_in[3];
    const float* be0= (const float*)d_in[4];
    const float* W1 = (const float*)d_in[5];
    const float* b1 = (const float*)d_in[6];
    const float* g1 = (const float*)d_in[7];
    const float* be1= (const float*)d_in[8];
    const float* W2 = (const float*)d_in[9];
    const float* b2 = (const float*)d_in[10];
    const float* g2 = (const float*)d_in[11];
    const float* be2= (const float*)d_in[12];
    float* outp = (float*)d_out;

    void *p_f0, *p_f1, *p_f2, *p_mx, *p_mn, *p_ps, *p_pq, *p_sum, *p_sq, *p_sc, *p_sh;
    cudaGetSymbolAddress(&p_f0, g_feat0);
    cudaGetSymbolAddress(&p_f1, g_feat1);
    cudaGetSymbolAddress(&p_f2, g_feat2);
    cudaGetSymbolAddress(&p_mx, g_mx);
    cudaGetSymbolAddress(&p_mn, g_mn);
    cudaGetSymbolAddress(&p_ps, g_psum);
    cudaGetSymbolAddress(&p_pq, g_psq);
    cudaGetSymbolAddress(&p_sum, g_sum);
    cudaGetSymbolAddress(&p_sq, g_sq);
    cudaGetSymbolAddress(&p_sc, g_scale);
    cudaGetSymbolAddress(&p_sh, g_shift);

    const int smemF = 3*NN*4;                 // 48KB coords for fps
    cudaFuncSetAttribute((const void*)fps_kernel,
                         cudaFuncAttributeMaxDynamicSharedMemorySize, smemF);
    const int smem1 = (64*4   + 4*MT)  * 4;   //  3 KB
    const int smem2 = (64*64  + 64*MT) * 4;   // 48 KB
    const int smem3 = (128*64 + 64*MT) * 4;   // 64 KB
    cudaFuncSetAttribute((const void*)conv_kernel<64,64,64,true,false>,
                         cudaFuncAttributeMaxDynamicSharedMemorySize, smem2);
    cudaFuncSetAttribute((const void*)conv_kernel<64,64,128,true,true>,
                         cudaFuncAttributeMaxDynamicSharedMemorySize, smem3);

    fps_kernel<<<BB, 512, smemF>>>(xyz);
    select_kernel<<<BB*NSAMPLE, 1024>>>(xyz);
    gather_kernel<<<(M_TOT+255)/256, 256>>>(xyz);

    // layer 1: 3 -> 64 (no input BN)
    conv_kernel<4,3,64,false,false><<<NBLK, 256, smem1>>>(
        (const float*)p_f0, W0, b0, nullptr, nullptr,
        (float*)p_f1, nullptr, (float*)p_ps, (float*)p_pq);
    reduce_kernel<<<dim3(64,2), 256>>>((const float*)p_ps, (const float*)p_pq,
                                       (float*)p_sum, (float*)p_sq);
    bn_kernel<<<1, 128>>>(g0, be0, 64);

    // layer 2: 64 -> 64 (BN1+ReLU applied on input)
    conv_kernel<64,64,64,true,false><<<NBLK, 256, smem2>>>(
        (const float*)p_f1, W1, b1, (const float*)p_sc, (const float*)p_sh,
        (float*)p_f2, nullptr, (float*)p_ps, (float*)p_pq);
    reduce_kernel<<<dim3(64,2), 256>>>((const float*)p_ps, (const float*)p_pq,
                                       (float*)p_sum, (float*)p_sq);
    bn_kernel<<<1, 128>>>(g1, be1, 64);

    // layer 3: 64 -> 128, k-reduced max/min output (BN2+ReLU applied on input)
    conv_kernel<64,64,128,true,true><<<NBLK, 256, smem3>>>(
        (const float*)p_f2, W2, b2, (const float*)p_sc, (const float*)p_sh,
        (float*)p_mx, (float*)p_mn, (float*)p_ps, (float*)p_pq);
    reduce_kernel<<<dim3(128,2), 256>>>((const float*)p_ps, (const float*)p_pq,
                                        (float*)p_sum, (float*)p_sq);
    bn_kernel<<<1, 128>>>(g2, be2, 128);

    // BN3 + ReLU on extremes -> features; then new_xyz transpose
    final_kernel<<<(FEAT_OUT+255)/256, 256>>>(outp);
    xyz_out_kernel<<<(BB*3*NPOINT+255)/256, 256>>>(outp + FEAT_OUT);
}